// round 14
// baseline (speedup 1.0000x reference)
#include <cuda_runtime.h>
#include <cuda_bf16.h>
#include <cstdint>

// EngramMemory — bucket-sorted fan-out (R13).
//
// tokens: (4, 4096) int32, tables: (8, 2048, 256) f32, out: (4, 4096, 2048) f32
// out[p][part*256 + d] = tables[part][h(part,p)][d]
//   h = fold over order-(2+oi) n-gram: h = (h*1000003 + tok + seed) & 2047,
//   seed = 1337 + 97*(2+oi) + 17*head, left zero-padded. u32 math throughout.
//
// Evidence: the direct gather runs at ~10.2 TB/s LTS = ~98% of the measured
// 6300 B/cyc chip cap -> only cutting L2 BYTES can go faster. Each table row
// is gathered 8x on average, so invert: bucket-sort the positions (k1), then
// read each needed row ONCE and fan it out to all matching output rows (k2).
// L2 traffic: 262 MB -> ~155 MB.
//
// k0: zero 16384 counters.
// k1: 16384 positions x 8 parts -> atomicAdd position into g_list[part][h].
//     (spread atomics over 16k addresses; deterministic output since writes
//      are idempotent per (p, part) regardless of list order.)
// k2: CTA = (part, 32 buckets); 8 groups of 64 threads; group loads one 1 KB
//     row (float4/thread) and stores it to every listed position.

namespace {
constexpr int B = 4;
constexpr int S = 4096;
constexpr int BS = 16384;
constexpr int NB = 2048;
constexpr int HD = 256;
constexpr int PARTS = 8;
constexpr int CAP = 40;                 // Binom(16384,1/2048): mean 8, +11 sigma
constexpr int NLISTS = PARTS * NB;      // 16384
constexpr unsigned PRIME = 1000003u;

__device__ unsigned g_cnt[NLISTS];
__device__ unsigned g_list[NLISTS * CAP];

__global__ void zero_kernel() {
    const int i = blockIdx.x * blockDim.x + threadIdx.x;
    if (i < NLISTS) g_cnt[i] = 0;
}

__global__ __launch_bounds__(256)
void hash_kernel(const int* __restrict__ tokens) {
    const int p = blockIdx.x * 256 + threadIdx.x;   // 0..16383
    const int s = p & (S - 1);
    const unsigned t0  = (unsigned)tokens[p];
    const unsigned tm1 = (s >= 1) ? (unsigned)tokens[p - 1] : 0u;
    const unsigned tm2 = (s >= 2) ? (unsigned)tokens[p - 2] : 0u;

    #pragma unroll
    for (int part = 0; part < PARTS; part++) {
        const int oi   = part >> 2;
        const int head = part & 3;
        const unsigned seed = 1337u + 97u * (unsigned)(2 + oi) + 17u * (unsigned)head;
        unsigned h;
        if (oi == 0) {                       // order 2: (t[-1], t[0])
            h = (tm1 + seed) & (NB - 1);
            h = (h * PRIME + t0 + seed) & (NB - 1);
        } else {                             // order 3: (t[-2], t[-1], t[0])
            h = (tm2 + seed) & (NB - 1);
            h = (h * PRIME + tm1 + seed) & (NB - 1);
            h = (h * PRIME + t0  + seed) & (NB - 1);
        }
        const unsigned li  = (unsigned)part * NB + h;
        const unsigned idx = atomicAdd(&g_cnt[li], 1u);
        if (idx < CAP) g_list[li * CAP + idx] = (unsigned)p;
    }
}

__global__ __launch_bounds__(512, 3)
void scatter_kernel(const float* __restrict__ tables,
                    float*       __restrict__ out) {
    const int part   = blockIdx.x >> 6;          // 0..7
    const int range  = blockIdx.x & 63;          // 32-bucket range
    const int grp    = threadIdx.x >> 6;         // 0..7
    const int lane64 = threadIdx.x & 63;         // float4 within the 1 KB row

    #pragma unroll
    for (int i = 0; i < 4; i++) {
        const int bucket = range * 32 + grp * 4 + i;
        const unsigned li = (unsigned)part * NB + bucket;

        // Read the table row once (64 threads x 16 B = 1 KB).
        const float4* src = reinterpret_cast<const float4*>(
            tables + ((size_t)part * NB + bucket) * HD) + lane64;
        const float4 v = __ldg(src);

        unsigned cnt = g_cnt[li];
        if (cnt > CAP) cnt = CAP;
        const unsigned* lst = &g_list[li * CAP];

        // Fan out: one store per matching output position.
        #pragma unroll 2
        for (unsigned j = 0; j < cnt; j++) {
            const unsigned p = __ldg(lst + j);
            float4* dst = reinterpret_cast<float4*>(
                out + (size_t)p * (PARTS * HD) + part * HD) + lane64;
            __stcs(dst, v);
        }
    }
}
} // namespace

extern "C" void kernel_launch(void* const* d_in, const int* in_sizes, int n_in,
                              void* d_out, int out_size) {
    // Resolve input order by element count: tokens = 16384, tables = 4194304.
    int ti = 0, wi = 1;
    if (n_in >= 2 && in_sizes[0] > in_sizes[1]) { ti = 1; wi = 0; }
    const int*   tokens = (const int*)d_in[ti];
    const float* tables = (const float*)d_in[wi];
    float*       out    = (float*)d_out;

    zero_kernel<<<(NLISTS + 511) / 512, 512>>>();
    hash_kernel<<<BS / 256, 256>>>(tokens);
    scatter_kernel<<<PARTS * 64, 512>>>(tables, out);
}